// round 11
// baseline (speedup 1.0000x reference)
#include <cuda_runtime.h>
#include <cuda_bf16.h>

#define BB      512     // batch
#define DD      256     // feature dim
#define NTILE   16      // 512/32 tiles per side
#define NTRI    136     // NTILE*(NTILE+1)/2 upper-triangular tiles
#define NGEMM   (NTRI * 2)   // 272 GEMM work units (tri tile x D-half)
#define ROWTGT  32u     // per tile-row: 16 tiles x 2 halves
#define MARGIN  0.2f

__device__ float g_simH[2][BB * BB];      // D-split partial sims (2 MB)
__device__ float g_partials[BB];          // per-anchor-row partial loss
__device__ unsigned int g_rowdone[NTILE]; // per-tile-row GEMM completion counters
__device__ unsigned int g_done;           // pair-done counter (reset by finalize)

__device__ __forceinline__ float blockReduceSum(float v, float* s_red) {
    #pragma unroll
    for (int o = 16; o > 0; o >>= 1) v += __shfl_down_sync(0xffffffffu, v, o);
    __syncthreads();
    int w = threadIdx.x >> 5, l = threadIdx.x & 31;
    if (l == 0) s_red[w] = v;
    __syncthreads();
    int nw = blockDim.x >> 5;
    if (w == 0) {
        v = (l < nw) ? s_red[l] : 0.0f;
        #pragma unroll
        for (int o = 16; o > 0; o >>= 1) v += __shfl_down_sync(0xffffffffu, v, o);
    }
    return v;  // valid in thread 0
}

// ---------------------------------------------------------------------------
// Fused kernel, fine-grained sync: blocks 0..271 compute one SYRK unit
// (32x32 tri tile x D-half) and bump the 1-2 row counters they complete.
// Every block then acquire-polls ONLY its own tile-row's counter (plain L2
// loads, no RMW) before running its anchor row's pair reduction.
// ---------------------------------------------------------------------------
__global__ __launch_bounds__(256)
void mcl_fused_kernel(const float* __restrict__ F, const int* __restrict__ labels,
                      float* __restrict__ out) {
    __shared__ float  AsT[32][34];     // GEMM phase
    __shared__ float  BsT[32][34];
    __shared__ int    s_lab[BB];       // pair phase
    __shared__ float4 s_pos4[132];     // 528 floats, padded positives
    __shared__ float  s_neg[BB];
    __shared__ int    s_pcnt[32], s_ncnt[32];
    __shared__ int    s_poff[32], s_noff[32];
    __shared__ int    s_cnt[2];
    __shared__ float  s_red[8];
    __shared__ int    s_hist[16];
    __shared__ int    s_isLast;

    const int t    = threadIdx.x;
    const int bid  = blockIdx.x;
    const int lane = t & 31;
    const int w    = t >> 5;           // 0..7
    float* s_pos = reinterpret_cast<float*>(s_pos4);

    // Pair-phase setup issued early (overlaps GEMM LDG latency).
    s_lab[t]       = labels[t];
    s_lab[t + 256] = labels[t + 256];
    if (t < 32) { s_pcnt[t] = 0; s_ncnt[t] = 0; }

    // ---------------- Phase 1: GEMM (blocks 0..NGEMM-1) ----------------
    if (bid < NGEMM) {
        const int tx   = t & 15, ty = t >> 4;
        const int half = bid & 1;
        int bi = 0, rem = bid >> 1;
        while (rem >= NTILE - bi) { rem -= NTILE - bi; bi++; }
        const int bk = bi + rem;
        const int i0 = bi * 32, k0 = bk * 32;

        const int lr = t >> 5;         // ld row group base (x8 rows via j)
        const int lc = t & 31;         // ld col (dd within chunk)
        const int dbase = half * 128;

        float c00 = 0.f, c01 = 0.f, c10 = 0.f, c11 = 0.f;
        float rA[4], rB[4];

        #pragma unroll
        for (int j = 0; j < 4; j++) {
            rA[j] = F[(size_t)(i0 + lr + j * 8) * DD + dbase + lc];
            rB[j] = F[(size_t)(k0 + lr + j * 8) * DD + dbase + lc];
        }

        #pragma unroll
        for (int c = 0; c < 4; c++) {
            #pragma unroll
            for (int j = 0; j < 4; j++) {
                AsT[lc][lr + j * 8] = rA[j];
                BsT[lc][lr + j * 8] = rB[j];
            }
            __syncthreads();
            if (c < 3) {
                const int dn = dbase + (c + 1) * 32;
                #pragma unroll
                for (int j = 0; j < 4; j++) {
                    rA[j] = F[(size_t)(i0 + lr + j * 8) * DD + dn + lc];
                    rB[j] = F[(size_t)(k0 + lr + j * 8) * DD + dn + lc];
                }
            }
            #pragma unroll
            for (int dd = 0; dd < 32; dd++) {
                float2 a  = *reinterpret_cast<float2*>(&AsT[dd][2 * ty]);
                float2 bv = *reinterpret_cast<float2*>(&BsT[dd][2 * tx]);
                c00 += a.x * bv.x; c01 += a.x * bv.y;
                c10 += a.y * bv.x; c11 += a.y * bv.y;
            }
            __syncthreads();
        }

        float* C = g_simH[half];
        *reinterpret_cast<float2*>(&C[(size_t)(i0 + 2 * ty)     * BB + k0 + 2 * tx]) = make_float2(c00, c01);
        *reinterpret_cast<float2*>(&C[(size_t)(i0 + 2 * ty + 1) * BB + k0 + 2 * tx]) = make_float2(c10, c11);
        if (bi != bk) {
            *reinterpret_cast<float2*>(&C[(size_t)(k0 + 2 * tx)     * BB + i0 + 2 * ty]) = make_float2(c00, c10);
            *reinterpret_cast<float2*>(&C[(size_t)(k0 + 2 * tx + 1) * BB + i0 + 2 * ty]) = make_float2(c01, c11);
        }
        __threadfence();          // release: tile stores visible before counters
        __syncthreads();
        if (t == 0) {
            atomicAdd(&g_rowdone[bi], 1u);
            if (bi != bk) atomicAdd(&g_rowdone[bk], 1u);
        }
    }

    // ---------------- Fine-grained row barrier (acquire-load poll) --------
    {
        const int R = bid >> 5;   // tile-row owning anchor row `bid`
        if (t == 0) {
            const unsigned int* addr = &g_rowdone[R];
            unsigned int v;
            while (true) {
                asm volatile("ld.global.acquire.gpu.u32 %0, [%1];"
                             : "=r"(v) : "l"(addr));
                if (v >= ROWTGT) break;
                __nanosleep(32);
            }
        }
        __syncthreads();
        __threadfence();          // order subsequent sim reads after acquire
    }

    // ---------------- Phase 2: pair row i = bid ----------------
    const int i  = bid;
    const int li = s_lab[i];
    const float* rowA = g_simH[0] + (size_t)i * BB;
    const float* rowB = g_simH[1] + (size_t)i * BB;
    const int kA = t, kB = t + 256;
    const float vA = rowA[kA] + rowB[kA];
    const float vB = rowA[kB] + rowB[kB];
    const bool eqA = (s_lab[kA] == li), eqB = (s_lab[kB] == li);
    const bool pA = (kA != i) && eqA, nA = (kA != i) && !eqA;
    const bool pB = (kB != i) && eqB, nB = (kB != i) && !eqB;
    const unsigned bpA = __ballot_sync(0xffffffffu, pA);
    const unsigned bnA = __ballot_sync(0xffffffffu, nA);
    const unsigned bpB = __ballot_sync(0xffffffffu, pB);
    const unsigned bnB = __ballot_sync(0xffffffffu, nB);
    if (lane == 0) {
        s_pcnt[w] = __popc(bpA); s_pcnt[8 + w] = __popc(bpB);
        s_ncnt[w] = __popc(bnA); s_ncnt[8 + w] = __popc(bnB);
    }
    __syncthreads();
    if (w == 0) {                       // exclusive scan of pos counts (16 live)
        int c = s_pcnt[lane], x = c;
        #pragma unroll
        for (int o = 1; o < 32; o <<= 1) {
            int y = __shfl_up_sync(0xffffffffu, x, o);
            if (lane >= o) x += y;
        }
        s_poff[lane] = x - c;
        if (lane == 31) s_cnt[0] = x;
    } else if (w == 1) {                // exclusive scan of neg counts
        int c = s_ncnt[lane], x = c;
        #pragma unroll
        for (int o = 1; o < 32; o <<= 1) {
            int y = __shfl_up_sync(0xffffffffu, x, o);
            if (lane >= o) x += y;
        }
        s_noff[lane] = x - c;
        if (lane == 31) s_cnt[1] = x;
    }
    __syncthreads();
    const unsigned lt = (1u << lane) - 1u;
    if (pA) s_pos[s_poff[w]     + __popc(bpA & lt)] = vA;
    if (pB) s_pos[s_poff[8 + w] + __popc(bpB & lt)] = vB;
    if (nA) s_neg[s_noff[w]     + __popc(bnA & lt)] = vA;
    if (nB) s_neg[s_noff[8 + w] + __popc(bnB & lt)] = vB;
    __syncthreads();

    const int P = s_cnt[0], N = s_cnt[1];
    if (t < 4) s_pos[P + t] = 1e30f;    // pad to multiple of 4 (max idx 514 < 528)
    __syncthreads();

    const float t0 = (t       < N) ? (MARGIN + s_neg[t])       : -1e30f;
    const float t1 = (t + 256 < N) ? (MARGIN + s_neg[t + 256]) : -1e30f;
    float a0 = 0.f, a1 = 0.f;
    const int P4 = (P + 3) >> 2;
    for (int pc = 0; pc < P4; pc++) {
        float4 pv = s_pos4[pc];
        a0 += fmaxf(0.f, t0 - pv.x) + fmaxf(0.f, t0 - pv.y)
            + fmaxf(0.f, t0 - pv.z) + fmaxf(0.f, t0 - pv.w);
        a1 += fmaxf(0.f, t1 - pv.x) + fmaxf(0.f, t1 - pv.y)
            + fmaxf(0.f, t1 - pv.z) + fmaxf(0.f, t1 - pv.w);
    }

    float total = blockReduceSum(a0 + a1, s_red);
    if (t == 0) {
        g_partials[i] = total;
        __threadfence();
        unsigned v = atomicAdd(&g_done, 1u);
        s_isLast = (v == BB - 1) ? 1 : 0;
    }
    __syncthreads();

    // ---------------- Finalize (last-finishing block) ----------------
    if (s_isLast) {
        __threadfence();
        float part = g_partials[t] + g_partials[t + 256];
        float loss_sum = blockReduceSum(part, s_red);

        if (t < 16) s_hist[t] = 0;
        __syncthreads();
        atomicAdd(&s_hist[s_lab[t]], 1);
        atomicAdd(&s_hist[s_lab[t + 256]], 1);
        __syncthreads();

        if (t == 0) {
            float nv = 0.0f;
            #pragma unroll
            for (int c = 0; c < 16; c++) {
                int hc = s_hist[c];
                if (hc >= 2 && hc < BB) nv += (float)hc;   // posc>0 && negc>0
            }
            int   cl    = s_lab[BB - 1];
            float pcl   = (float)(s_hist[cl] - 1);
            float ncl   = (float)(BB - s_hist[cl]);
            float denom = nv * pcl * ncl;
            out[0] = (denom > 0.0f) ? (loss_sum / denom) : 0.0f;
            g_done = 0;   // reset for next graph replay
        }
        if (t < NTILE) g_rowdone[t] = 0;   // reset row counters
    }
}

extern "C" void kernel_launch(void* const* d_in, const int* in_sizes, int n_in,
                              void* d_out, int out_size) {
    const float* F      = (const float*)d_in[0];
    const int*   labels = (const int*)d_in[1];
    float*       out    = (float*)d_out;
    (void)in_sizes; (void)n_in; (void)out_size;

    mcl_fused_kernel<<<BB, 256>>>(F, labels, out);
}

// round 12
// speedup vs baseline: 1.1065x; 1.1065x over previous
#include <cuda_runtime.h>
#include <cuda_bf16.h>

#define BB      512     // batch
#define DD      256     // feature dim
#define NT2     8       // 512/64 tiles per side
#define NTRI2   36      // NT2*(NT2+1)/2 triangular 64x64 tiles
#define NQ      8       // K split: 8 chunks of 32
#define NGEMM   (NTRI2 * NQ)   // 288 blocks
#define MARGIN  0.2f

__device__ float g_simQ[NQ][BB * BB];   // K-split partial sims (8 MB)
__device__ float g_partials[BB];        // per-anchor-row partial loss
__device__ unsigned int g_done;         // zero-init; reset by finalize

__device__ __forceinline__ float blockReduceSum(float v, float* s_red) {
    #pragma unroll
    for (int o = 16; o > 0; o >>= 1) v += __shfl_down_sync(0xffffffffu, v, o);
    __syncthreads();
    int w = threadIdx.x >> 5, l = threadIdx.x & 31;
    if (l == 0) s_red[w] = v;
    __syncthreads();
    int nw = blockDim.x >> 5;
    if (w == 0) {
        v = (l < nw) ? s_red[l] : 0.0f;
        #pragma unroll
        for (int o = 16; o > 0; o >>= 1) v += __shfl_down_sync(0xffffffffu, v, o);
    }
    return v;  // valid in thread 0
}

// ---------------------------------------------------------------------------
// Kernel 0: symmetric SYRK, 64x64 tiles, 4x4 micro-tiles, K-chunk of 32.
// blockIdx.x = tri*8 + q. 256 threads = 16x16 grid of 4x4 micro-tiles.
// LDS.128 A (warp-broadcast) + LDS.128 B per 16 FFMA -> FFMA-issue bound.
// ---------------------------------------------------------------------------
__global__ __launch_bounds__(256)
void mcl_gemm_kernel(const float* __restrict__ F) {
    __shared__ __align__(16) float As[32][68];   // [dd][row], pad 68
    __shared__ __align__(16) float Bs[32][68];

    const int t  = threadIdx.x;
    const int tx = t & 15, ty = t >> 4;
    const int q  = blockIdx.x & 7;
    int bi = 0, rem = blockIdx.x >> 3;
    while (rem >= NT2 - bi) { rem -= NT2 - bi; bi++; }
    const int bk = bi + rem;
    const int i0 = bi * 64, k0 = bk * 64;
    const int dbase = q * 32;

    const int lc = t & 31;      // dd within chunk
    const int lr = t >> 5;      // row group base (rows lr + 8j)

    // load both 64x32 slabs (coalesced: consecutive t -> consecutive d)
    #pragma unroll
    for (int j = 0; j < 8; j++) {
        As[lc][lr + 8 * j] = F[(size_t)(i0 + lr + 8 * j) * DD + dbase + lc];
        Bs[lc][lr + 8 * j] = F[(size_t)(k0 + lr + 8 * j) * DD + dbase + lc];
    }
    __syncthreads();

    float4 acc0 = {0,0,0,0}, acc1 = {0,0,0,0}, acc2 = {0,0,0,0}, acc3 = {0,0,0,0};
    #pragma unroll 8
    for (int dd = 0; dd < 32; dd++) {
        float4 a = *reinterpret_cast<float4*>(&As[dd][4 * ty]);
        float4 b = *reinterpret_cast<float4*>(&Bs[dd][4 * tx]);
        acc0.x += a.x * b.x; acc0.y += a.x * b.y; acc0.z += a.x * b.z; acc0.w += a.x * b.w;
        acc1.x += a.y * b.x; acc1.y += a.y * b.y; acc1.z += a.y * b.z; acc1.w += a.y * b.w;
        acc2.x += a.z * b.x; acc2.y += a.z * b.y; acc2.z += a.z * b.z; acc2.w += a.z * b.w;
        acc3.x += a.w * b.x; acc3.y += a.w * b.y; acc3.z += a.w * b.z; acc3.w += a.w * b.w;
    }

    float* C = g_simQ[q];
    const int r0 = i0 + 4 * ty, c0 = k0 + 4 * tx;
    *reinterpret_cast<float4*>(&C[(size_t)(r0 + 0) * BB + c0]) = acc0;
    *reinterpret_cast<float4*>(&C[(size_t)(r0 + 1) * BB + c0]) = acc1;
    *reinterpret_cast<float4*>(&C[(size_t)(r0 + 2) * BB + c0]) = acc2;
    *reinterpret_cast<float4*>(&C[(size_t)(r0 + 3) * BB + c0]) = acc3;
    if (bi != bk) {   // mirror (transposed scalar stores)
        C[(size_t)(c0 + 0) * BB + r0] = acc0.x; C[(size_t)(c0 + 0) * BB + r0 + 1] = acc1.x;
        C[(size_t)(c0 + 0) * BB + r0 + 2] = acc2.x; C[(size_t)(c0 + 0) * BB + r0 + 3] = acc3.x;
        C[(size_t)(c0 + 1) * BB + r0] = acc0.y; C[(size_t)(c0 + 1) * BB + r0 + 1] = acc1.y;
        C[(size_t)(c0 + 1) * BB + r0 + 2] = acc2.y; C[(size_t)(c0 + 1) * BB + r0 + 3] = acc3.y;
        C[(size_t)(c0 + 2) * BB + r0] = acc0.z; C[(size_t)(c0 + 2) * BB + r0 + 1] = acc1.z;
        C[(size_t)(c0 + 2) * BB + r0 + 2] = acc2.z; C[(size_t)(c0 + 2) * BB + r0 + 3] = acc3.z;
        C[(size_t)(c0 + 3) * BB + r0] = acc0.w; C[(size_t)(c0 + 3) * BB + r0 + 1] = acc1.w;
        C[(size_t)(c0 + 3) * BB + r0 + 2] = acc2.w; C[(size_t)(c0 + 3) * BB + r0 + 3] = acc3.w;
    }
}

// ---------------------------------------------------------------------------
// Kernel 1: one block per anchor row. Positives compacted via ballot scan;
// negatives processed in place (predicated per thread — no compaction).
// Fused finalize in the last-finishing block.
// ---------------------------------------------------------------------------
__global__ __launch_bounds__(256)
void mcl_pair_kernel(const int* __restrict__ labels, float* __restrict__ out) {
    __shared__ int    s_lab[BB];
    __shared__ float4 s_pos4[132];     // 528 floats, padded positives
    __shared__ int    s_pcnt[32];
    __shared__ int    s_poff[32];
    __shared__ int    s_cnt;
    __shared__ float  s_red[8];
    __shared__ int    s_hist[16];
    __shared__ int    s_isLast;

    const int t    = threadIdx.x;
    const int i    = blockIdx.x;
    const int lane = t & 31;
    const int w    = t >> 5;           // 0..7
    float* s_pos = reinterpret_cast<float*>(s_pos4);

    s_lab[t]       = labels[t];
    s_lab[t + 256] = labels[t + 256];
    if (t < 32) s_pcnt[t] = 0;
    __syncthreads();

    const int li = s_lab[i];
    const int kA = t, kB = t + 256;
    float vA = 0.f, vB = 0.f;
    #pragma unroll
    for (int q = 0; q < NQ; q++) {
        vA += g_simQ[q][(size_t)i * BB + kA];
        vB += g_simQ[q][(size_t)i * BB + kB];
    }
    const bool eqA = (s_lab[kA] == li), eqB = (s_lab[kB] == li);
    const bool pA = (kA != i) && eqA, pB = (kB != i) && eqB;
    const unsigned bpA = __ballot_sync(0xffffffffu, pA);
    const unsigned bpB = __ballot_sync(0xffffffffu, pB);
    if (lane == 0) { s_pcnt[w] = __popc(bpA); s_pcnt[8 + w] = __popc(bpB); }
    __syncthreads();
    if (w == 0) {                       // exclusive scan of 16 live pos counts
        int c = s_pcnt[lane], x = c;
        #pragma unroll
        for (int o = 1; o < 32; o <<= 1) {
            int y = __shfl_up_sync(0xffffffffu, x, o);
            if (lane >= o) x += y;
        }
        s_poff[lane] = x - c;
        if (lane == 31) s_cnt = x;
    }
    __syncthreads();
    const unsigned lt = (1u << lane) - 1u;
    if (pA) s_pos[s_poff[w]     + __popc(bpA & lt)] = vA;
    if (pB) s_pos[s_poff[8 + w] + __popc(bpB & lt)] = vB;
    __syncthreads();

    const int P = s_cnt;
    if (t < 4) s_pos[P + t] = 1e30f;    // pad to multiple of 4 (max idx 514 < 528)
    __syncthreads();

    // negatives in place: thread's own kA/kB slots, predicated
    const float t0 = ((kA != i) && !eqA) ? (MARGIN + vA) : -1e30f;
    const float t1 = ((kB != i) && !eqB) ? (MARGIN + vB) : -1e30f;
    float a0 = 0.f, a1 = 0.f;
    const int P4 = (P + 3) >> 2;
    for (int pc = 0; pc < P4; pc++) {
        float4 pv = s_pos4[pc];
        a0 += fmaxf(0.f, t0 - pv.x) + fmaxf(0.f, t0 - pv.y)
            + fmaxf(0.f, t0 - pv.z) + fmaxf(0.f, t0 - pv.w);
        a1 += fmaxf(0.f, t1 - pv.x) + fmaxf(0.f, t1 - pv.y)
            + fmaxf(0.f, t1 - pv.z) + fmaxf(0.f, t1 - pv.w);
    }

    float total = blockReduceSum(a0 + a1, s_red);
    if (t == 0) {
        g_partials[i] = total;
        __threadfence();
        unsigned v = atomicAdd(&g_done, 1u);
        s_isLast = (v == BB - 1) ? 1 : 0;
    }
    __syncthreads();

    // ---------------- Finalize (last-finishing block) ----------------
    if (s_isLast) {
        __threadfence();
        float part = g_partials[t] + g_partials[t + 256];
        float loss_sum = blockReduceSum(part, s_red);

        if (t < 16) s_hist[t] = 0;
        __syncthreads();
        atomicAdd(&s_hist[s_lab[t]], 1);
        atomicAdd(&s_hist[s_lab[t + 256]], 1);
        __syncthreads();

        if (t == 0) {
            float nv = 0.0f;
            #pragma unroll
            for (int c = 0; c < 16; c++) {
                int hc = s_hist[c];
                if (hc >= 2 && hc < BB) nv += (float)hc;   // posc>0 && negc>0
            }
            int   cl    = s_lab[BB - 1];
            float pcl   = (float)(s_hist[cl] - 1);
            float ncl   = (float)(BB - s_hist[cl]);
            float denom = nv * pcl * ncl;
            out[0] = (denom > 0.0f) ? (loss_sum / denom) : 0.0f;
            g_done = 0;   // reset for next graph replay
        }
    }
}

extern "C" void kernel_launch(void* const* d_in, const int* in_sizes, int n_in,
                              void* d_out, int out_size) {
    const float* F      = (const float*)d_in[0];
    const int*   labels = (const int*)d_in[1];
    float*       out    = (float*)d_out;
    (void)in_sizes; (void)n_in; (void)out_size;

    mcl_gemm_kernel<<<NGEMM, 256>>>(F);
    mcl_pair_kernel<<<BB, 256>>>(labels, out);
}